// round 10
// baseline (speedup 1.0000x reference)
#include <cuda_runtime.h>
#include <cuda_bf16.h>
#include <cuda_fp16.h>
#include <mma.h>

using namespace nvcuda;

#define NA 100000
#define NB 50000
#define DIM 128
#define EE 1000000

// ---- static device scratch ----
__device__ __half g_h_ab[(size_t)NA * DIM];   // x_a @ W_ab  -> out_b
__device__ __half g_h_ba[(size_t)NB * DIM];   // x_b @ W_ba  -> out_a
__device__ __half g_h_aa[(size_t)NA * DIM];   // x_a @ W_aa  -> out_a

__device__ int g_deg_s_ab[NA];
__device__ int g_deg_t_ab[NB];
__device__ int g_deg_s_ba[NB];
__device__ int g_deg_t_ba[NA];
__device__ int g_deg_s_aa[NA];
__device__ int g_deg_t_aa[NA];

// CSR-by-dst
__device__ int g_rs_ab[NB];
__device__ int g_rs_ba[NA];
__device__ int g_rs_aa[NA];
__device__ int g_cur_ab[NB];
__device__ int g_cur_ba[NA];
__device__ int g_cur_aa[NA];
__device__ int g_csr_ab[EE];
__device__ int g_csr_ba[EE];
__device__ int g_csr_aa[EE];

// dyn smem layout for the wmma GEMM
#define AH_LD 136
#define SMEM_AH_BYTES (128 * AH_LD * 2)          // 34816
#define SMEM_WH_BYTES (128 * 128 * 2)            // 32768
#define SMEM_ST_BYTES (8 * 16 * 20 * 4)          // 10240
#define GEMM_SMEM (SMEM_AH_BYTES + SMEM_WH_BYTES + SMEM_ST_BYTES)

__global__ void gemm_wmma_kernel(const float* __restrict__ X,
                                 const float* __restrict__ W,
                                 __half* __restrict__ H, int nrows);

// ---- streams/events for fork-join overlap ----
static cudaStream_t g_s1;
static cudaEvent_t g_evFork, g_evGemmA, g_evCsr, g_evTailB;
static struct InitOnce {
    InitOnce() {
        cudaStreamCreateWithFlags(&g_s1, cudaStreamNonBlocking);
        cudaEventCreateWithFlags(&g_evFork, cudaEventDisableTiming);
        cudaEventCreateWithFlags(&g_evGemmA, cudaEventDisableTiming);
        cudaEventCreateWithFlags(&g_evCsr, cudaEventDisableTiming);
        cudaEventCreateWithFlags(&g_evTailB, cudaEventDisableTiming);
        cudaFuncSetAttribute(gemm_wmma_kernel,
                             cudaFuncAttributeMaxDynamicSharedMemorySize, GEMM_SMEM);
    }
} g_initOnce;

// ---------------------------------------------------------------------
__global__ void zero_kernel() {
    int i = blockIdx.x * blockDim.x + threadIdx.x;
    int stride = gridDim.x * blockDim.x;
    for (int j = i; j < NA; j += stride) {
        g_deg_s_ab[j] = 0;
        g_deg_t_ba[j] = 0;
        g_deg_s_aa[j] = 0;
        g_deg_t_aa[j] = 0;
    }
    for (int j = i; j < NB; j += stride) {
        g_deg_t_ab[j] = 0;
        g_deg_s_ba[j] = 0;
    }
}

// ---------------------------------------------------------------------
__global__ void degree_kernel(const int* __restrict__ src_ab, const int* __restrict__ dst_ab,
                              const int* __restrict__ src_ba, const int* __restrict__ dst_ba,
                              const int* __restrict__ src_aa, const int* __restrict__ dst_aa) {
    int i = blockIdx.x * blockDim.x + threadIdx.x;
    if (i >= EE) return;
    atomicAdd(&g_deg_s_ab[src_ab[i]], 1);
    atomicAdd(&g_deg_t_ab[dst_ab[i]], 1);
    atomicAdd(&g_deg_s_ba[src_ba[i]], 1);
    atomicAdd(&g_deg_t_ba[dst_ba[i]], 1);
    atomicAdd(&g_deg_s_aa[src_aa[i]], 1);
    atomicAdd(&g_deg_t_aa[dst_aa[i]], 1);
}

// ---------------------------------------------------------------------
__global__ __launch_bounds__(1024) void scan3_kernel() {
    const int* deg;
    int n;
    int* rs;
    int* cur;
    if (blockIdx.x == 0)      { deg = g_deg_t_ab; n = NB; rs = g_rs_ab; cur = g_cur_ab; }
    else if (blockIdx.x == 1) { deg = g_deg_t_ba; n = NA; rs = g_rs_ba; cur = g_cur_ba; }
    else                      { deg = g_deg_t_aa; n = NA; rs = g_rs_aa; cur = g_cur_aa; }

    const int t = threadIdx.x;
    const int chunk = (n + 1023) >> 10;
    const int lo = t * chunk;
    const int hi = min(lo + chunk, n);

    int s = 0;
    for (int i = lo; i < hi; i++) s += deg[i];

    __shared__ int sm[1024];
    sm[t] = s;
    __syncthreads();
    for (int off = 1; off < 1024; off <<= 1) {
        int v = (t >= off) ? sm[t - off] : 0;
        __syncthreads();
        sm[t] += v;
        __syncthreads();
    }
    int base = (t > 0) ? sm[t - 1] : 0;
    for (int i = lo; i < hi; i++) {
        rs[i] = base;
        cur[i] = base;
        base += deg[i];
    }
}

// ---------------------------------------------------------------------
__global__ void fill_kernel(const int* __restrict__ src_ab, const int* __restrict__ dst_ab,
                            const int* __restrict__ src_ba, const int* __restrict__ dst_ba,
                            const int* __restrict__ src_aa, const int* __restrict__ dst_aa) {
    int i = blockIdx.x * blockDim.x + threadIdx.x;
    if (i >= EE) return;
    int p;
    p = atomicAdd(&g_cur_ab[dst_ab[i]], 1); g_csr_ab[p] = src_ab[i];
    p = atomicAdd(&g_cur_ba[dst_ba[i]], 1); g_csr_ba[p] = src_ba[i];
    p = atomicAdd(&g_cur_aa[dst_aa[i]], 1); g_csr_aa[p] = src_aa[i];
}

// ---------------------------------------------------------------------
// Tensor-core GEMM: H(fp16) = X(fp32->fp16) @ W(fp32->fp16), fp32 accum.
// BM=128 rows per block, full 128-col output. 256 threads = 8 warps,
// warp w owns rows 16w..16w+15, 8 wmma 16x16x16 tiles across N.
// ---------------------------------------------------------------------
__global__ __launch_bounds__(256) void gemm_wmma_kernel(const float* __restrict__ X,
                                                        const float* __restrict__ W,
                                                        __half* __restrict__ H, int nrows) {
    extern __shared__ char smem[];
    __half* Ah = reinterpret_cast<__half*>(smem);                       // [128][AH_LD]
    __half* Wh = reinterpret_cast<__half*>(smem + SMEM_AH_BYTES);       // [128][128]
    float*  St = reinterpret_cast<float*>(smem + SMEM_AH_BYTES + SMEM_WH_BYTES); // [8][16*20]

    const int t = threadIdx.x;
    const int warp = t >> 5;
    const int lane = t & 31;
    const int row0 = blockIdx.x * 128;

    // Load A tile (128 x 128 fp32 -> fp16), zero-pad OOB rows.
    for (int i = t; i < 128 * 32; i += 256) {      // 4096 float4
        int r = i >> 5;
        int c4 = (i & 31) * 4;
        float4 v = make_float4(0.f, 0.f, 0.f, 0.f);
        if (row0 + r < nrows)
            v = *reinterpret_cast<const float4*>(&X[(size_t)(row0 + r) * DIM + c4]);
        __half2 h0 = __floats2half2_rn(v.x, v.y);
        __half2 h1 = __floats2half2_rn(v.z, v.w);
        uint2 u = make_uint2(*reinterpret_cast<unsigned*>(&h0),
                             *reinterpret_cast<unsigned*>(&h1));
        *reinterpret_cast<uint2*>(&Ah[r * AH_LD + c4]) = u;
    }
    // Load W (128 x 128 fp32 -> fp16)
    for (int i = t; i < 128 * 32; i += 256) {
        int r = i >> 5;
        int c4 = (i & 31) * 4;
        float4 v = *reinterpret_cast<const float4*>(&W[(size_t)r * DIM + c4]);
        __half2 h0 = __floats2half2_rn(v.x, v.y);
        __half2 h1 = __floats2half2_rn(v.z, v.w);
        uint2 u = make_uint2(*reinterpret_cast<unsigned*>(&h0),
                             *reinterpret_cast<unsigned*>(&h1));
        *reinterpret_cast<uint2*>(&Wh[r * 128 + c4]) = u;
    }
    __syncthreads();

    wmma::fragment<wmma::accumulator, 16, 16, 16, float> acc[8];
#pragma unroll
    for (int n = 0; n < 8; n++) wmma::fill_fragment(acc[n], 0.f);

#pragma unroll
    for (int k = 0; k < 8; k++) {
        wmma::fragment<wmma::matrix_a, 16, 16, 16, __half, wmma::row_major> a;
        wmma::load_matrix_sync(a, &Ah[(warp * 16) * AH_LD + k * 16], AH_LD);
#pragma unroll
        for (int n = 0; n < 8; n++) {
            wmma::fragment<wmma::matrix_b, 16, 16, 16, __half, wmma::row_major> b;
            wmma::load_matrix_sync(b, &Wh[(k * 16) * 128 + n * 16], 128);
            wmma::mma_sync(acc[n], a, b, acc[n]);
        }
    }

    // Stage fp32 -> convert -> fp16 global, one 16x16 tile at a time.
    float* st = St + warp * (16 * 20);
#pragma unroll
    for (int n = 0; n < 8; n++) {
        wmma::store_matrix_sync(st, acc[n], 20, wmma::mem_row_major);
        __syncwarp();
        int r = lane >> 1;
        int c0 = (lane & 1) * 8;
        int grow = row0 + warp * 16 + r;
        if (grow < nrows) {
            __half2 hp[4];
#pragma unroll
            for (int j = 0; j < 4; j++)
                hp[j] = __floats2half2_rn(st[r * 20 + c0 + 2 * j],
                                          st[r * 20 + c0 + 2 * j + 1]);
            uint4 u = make_uint4(*reinterpret_cast<unsigned*>(&hp[0]),
                                 *reinterpret_cast<unsigned*>(&hp[1]),
                                 *reinterpret_cast<unsigned*>(&hp[2]),
                                 *reinterpret_cast<unsigned*>(&hp[3]));
            *reinterpret_cast<uint4*>(&H[(size_t)grow * DIM + n * 16 + c0]) = u;
        }
        __syncwarp();
    }
}

// ---------------------------------------------------------------------
// Warp-per-node gather; fp16 h rows, fp32 accumulation.
// ---------------------------------------------------------------------
__device__ __forceinline__ float4 gather_accum(const int* __restrict__ csr,
                                               const int* __restrict__ deg_s,
                                               int start, int cnt,
                                               const __half* __restrict__ h, int lane) {
    float4 acc = make_float4(0.f, 0.f, 0.f, 0.f);
    int j = 0;
    while (j < cnt) {
        int m = min(32, cnt - j);
        int idx = 0;
        float inv = 0.f;
        if (lane < m) {
            idx = __ldcs(&csr[start + j + lane]);
            inv = rsqrtf((float)deg_s[idx]);
        }
#pragma unroll 4
        for (int k = 0; k < m; k++) {
            int s = __shfl_sync(0xffffffffu, idx, k);
            float iv = __shfl_sync(0xffffffffu, inv, k);
            uint2 u = *reinterpret_cast<const uint2*>(&h[(size_t)s * DIM + lane * 4]);
            __half2 p0 = *reinterpret_cast<__half2*>(&u.x);
            __half2 p1 = *reinterpret_cast<__half2*>(&u.y);
            float2 f0 = __half22float2(p0);
            float2 f1 = __half22float2(p1);
            acc.x += f0.x * iv; acc.y += f0.y * iv;
            acc.z += f1.x * iv; acc.w += f1.y * iv;
        }
        j += m;
    }
    return acc;
}

__global__ __launch_bounds__(256) void gather_a_kernel(float* __restrict__ out_a) {
    int gw = blockIdx.x * (blockDim.x >> 5) + (threadIdx.x >> 5);
    int lane = threadIdx.x & 31;
    if (gw >= NA) return;
    int d = gw;
    int c_ba = g_deg_t_ba[d];
    int c_aa = g_deg_t_aa[d];
    float4 s_ba = gather_accum(g_csr_ba, g_deg_s_ba, g_rs_ba[d], c_ba, g_h_ba, lane);
    float4 s_aa = gather_accum(g_csr_aa, g_deg_s_aa, g_rs_aa[d], c_aa, g_h_aa, lane);
    float rb = (c_ba > 0) ? rsqrtf((float)c_ba) * 0.5f : 0.f;
    float ra = (c_aa > 0) ? rsqrtf((float)c_aa) * 0.5f : 0.f;
    float4 v;
    v.x = fmaxf(s_ba.x * rb + s_aa.x * ra, 0.f);
    v.y = fmaxf(s_ba.y * rb + s_aa.y * ra, 0.f);
    v.z = fmaxf(s_ba.z * rb + s_aa.z * ra, 0.f);
    v.w = fmaxf(s_ba.w * rb + s_aa.w * ra, 0.f);
    __stcs(reinterpret_cast<float4*>(&out_a[(size_t)d * DIM + lane * 4]), v);
}

__global__ __launch_bounds__(256) void gather_b_kernel(float* __restrict__ out_b) {
    int gw = blockIdx.x * (blockDim.x >> 5) + (threadIdx.x >> 5);
    int lane = threadIdx.x & 31;
    if (gw >= NB) return;
    int d = gw;
    int c_ab = g_deg_t_ab[d];
    float4 s_ab = gather_accum(g_csr_ab, g_deg_s_ab, g_rs_ab[d], c_ab, g_h_ab, lane);
    float r = (c_ab > 0) ? rsqrtf((float)c_ab) : 0.f;
    float4 v;
    v.x = fmaxf(s_ab.x * r, 0.f);
    v.y = fmaxf(s_ab.y * r, 0.f);
    v.z = fmaxf(s_ab.z * r, 0.f);
    v.w = fmaxf(s_ab.w * r, 0.f);
    __stcs(reinterpret_cast<float4*>(&out_b[(size_t)d * DIM + lane * 4]), v);
}

// ---------------------------------------------------------------------
extern "C" void kernel_launch(void* const* d_in, const int* in_sizes, int n_in,
                              void* d_out, int out_size) {
    const float* x_a  = (const float*)d_in[0];
    const float* x_b  = (const float*)d_in[1];
    const float* W_ab = (const float*)d_in[2];
    const float* W_ba = (const float*)d_in[3];
    const float* W_aa = (const float*)d_in[4];
    const int* src_ab = (const int*)d_in[5];
    const int* dst_ab = (const int*)d_in[6];
    const int* src_ba = (const int*)d_in[7];
    const int* dst_ba = (const int*)d_in[8];
    const int* src_aa = (const int*)d_in[9];
    const int* dst_aa = (const int*)d_in[10];

    float* out   = (float*)d_out;
    float* out_a = out;                       // [NA,128]
    float* out_b = out + (size_t)NA * DIM;    // [NB,128]

    __half *h_ab, *h_ba, *h_aa;
    cudaGetSymbolAddress((void**)&h_ab, g_h_ab);
    cudaGetSymbolAddress((void**)&h_ba, g_h_ba);
    cudaGetSymbolAddress((void**)&h_aa, g_h_aa);

    // ---- fork: side stream runs the 3 GEMMs (no degree dependency) ----
    cudaEventRecord(g_evFork, 0);
    cudaStreamWaitEvent(g_s1, g_evFork, 0);

    gemm_wmma_kernel<<<(NB + 127) / 128, 256, GEMM_SMEM, g_s1>>>(x_b, W_ba, h_ba, NB);
    gemm_wmma_kernel<<<(NA + 127) / 128, 256, GEMM_SMEM, g_s1>>>(x_a, W_aa, h_aa, NA);
    cudaEventRecord(g_evGemmA, g_s1);                    // h_ba + h_aa ready
    gemm_wmma_kernel<<<(NA + 127) / 128, 256, GEMM_SMEM, g_s1>>>(x_a, W_ab, h_ab, NA);

    // ---- main stream: CSR build ----
    zero_kernel<<<512, 256>>>();
    degree_kernel<<<(EE + 255) / 256, 256>>>(src_ab, dst_ab, src_ba, dst_ba, src_aa, dst_aa);
    scan3_kernel<<<3, 1024>>>();
    fill_kernel<<<(EE + 255) / 256, 256>>>(src_ab, dst_ab, src_ba, dst_ba, src_aa, dst_aa);
    cudaEventRecord(g_evCsr, 0);                         // CSR + degrees ready

    // gather_a on main stream: needs CSR (in-stream) + h_ba/h_aa (event)
    cudaStreamWaitEvent(0, g_evGemmA, 0);
    gather_a_kernel<<<(NA + 7) / 8, 256>>>(out_a);

    // gather_b on side stream: needs h_ab (in-stream) + CSR (event)
    cudaStreamWaitEvent(g_s1, g_evCsr, 0);
    gather_b_kernel<<<(NB + 7) / 8, 256, 0, g_s1>>>(out_b);
    cudaEventRecord(g_evTailB, g_s1);

    // join
    cudaStreamWaitEvent(0, g_evTailB, 0);
}

// round 11
// speedup vs baseline: 1.0752x; 1.0752x over previous
#include <cuda_runtime.h>
#include <cuda_bf16.h>
#include <cuda_fp16.h>
#include <mma.h>

using namespace nvcuda;

#define NA 100000
#define NB 50000
#define DIM 128
#define EE 1000000

// ---- static device scratch ----
__device__ __half g_h_ab[(size_t)NA * DIM];   // x_a @ W_ab  -> out_b
__device__ __half g_h_ba[(size_t)NB * DIM];   // x_b @ W_ba  -> out_a
__device__ __half g_h_aa[(size_t)NA * DIM];   // x_a @ W_aa  -> out_a

__device__ int g_deg_s_ab[NA];
__device__ int g_deg_t_ab[NB];
__device__ int g_deg_s_ba[NB];
__device__ int g_deg_t_ba[NA];
__device__ int g_deg_s_aa[NA];
__device__ int g_deg_t_aa[NA];

// CSR-by-dst
__device__ int g_rs_ab[NB];
__device__ int g_rs_ba[NA];
__device__ int g_rs_aa[NA];
__device__ int g_cur_ab[NB];
__device__ int g_cur_ba[NA];
__device__ int g_cur_aa[NA];
__device__ int g_csr_ab[EE];
__device__ int g_csr_ba[EE];
__device__ int g_csr_aa[EE];

// dyn smem layout for the wmma v2 GEMM (BM=64, 4 warps)
#define AH_LD 136
#define WH_LD 136
#define SMEM_AH_BYTES (64 * AH_LD * 2)           // 17408
#define SMEM_WH_BYTES (128 * WH_LD * 2)          // 34816
#define SMEM_ST_BYTES (4 * 16 * 20 * 4)          // 5120
#define GEMM_SMEM (SMEM_AH_BYTES + SMEM_WH_BYTES + SMEM_ST_BYTES)   // 57344

__global__ void gemm_wmma_kernel(const float* __restrict__ X,
                                 const float* __restrict__ W,
                                 __half* __restrict__ H, int nrows);

// ---- streams/events for fork-join overlap ----
static cudaStream_t g_s1;
static cudaEvent_t g_evFork, g_evGemmA, g_evCsr, g_evTailB;
static struct InitOnce {
    InitOnce() {
        cudaStreamCreateWithFlags(&g_s1, cudaStreamNonBlocking);
        cudaEventCreateWithFlags(&g_evFork, cudaEventDisableTiming);
        cudaEventCreateWithFlags(&g_evGemmA, cudaEventDisableTiming);
        cudaEventCreateWithFlags(&g_evCsr, cudaEventDisableTiming);
        cudaEventCreateWithFlags(&g_evTailB, cudaEventDisableTiming);
        cudaFuncSetAttribute(gemm_wmma_kernel,
                             cudaFuncAttributeMaxDynamicSharedMemorySize, GEMM_SMEM);
    }
} g_initOnce;

// ---------------------------------------------------------------------
__global__ void zero_kernel() {
    int i = blockIdx.x * blockDim.x + threadIdx.x;
    int stride = gridDim.x * blockDim.x;
    for (int j = i; j < NA; j += stride) {
        g_deg_s_ab[j] = 0;
        g_deg_t_ba[j] = 0;
        g_deg_s_aa[j] = 0;
        g_deg_t_aa[j] = 0;
    }
    for (int j = i; j < NB; j += stride) {
        g_deg_t_ab[j] = 0;
        g_deg_s_ba[j] = 0;
    }
}

// ---------------------------------------------------------------------
__global__ void degree_kernel(const int* __restrict__ src_ab, const int* __restrict__ dst_ab,
                              const int* __restrict__ src_ba, const int* __restrict__ dst_ba,
                              const int* __restrict__ src_aa, const int* __restrict__ dst_aa) {
    int i = blockIdx.x * blockDim.x + threadIdx.x;
    if (i >= EE) return;
    atomicAdd(&g_deg_s_ab[src_ab[i]], 1);
    atomicAdd(&g_deg_t_ab[dst_ab[i]], 1);
    atomicAdd(&g_deg_s_ba[src_ba[i]], 1);
    atomicAdd(&g_deg_t_ba[dst_ba[i]], 1);
    atomicAdd(&g_deg_s_aa[src_aa[i]], 1);
    atomicAdd(&g_deg_t_aa[dst_aa[i]], 1);
}

// ---------------------------------------------------------------------
__global__ __launch_bounds__(1024) void scan3_kernel() {
    const int* deg;
    int n;
    int* rs;
    int* cur;
    if (blockIdx.x == 0)      { deg = g_deg_t_ab; n = NB; rs = g_rs_ab; cur = g_cur_ab; }
    else if (blockIdx.x == 1) { deg = g_deg_t_ba; n = NA; rs = g_rs_ba; cur = g_cur_ba; }
    else                      { deg = g_deg_t_aa; n = NA; rs = g_rs_aa; cur = g_cur_aa; }

    const int t = threadIdx.x;
    const int chunk = (n + 1023) >> 10;
    const int lo = t * chunk;
    const int hi = min(lo + chunk, n);

    int s = 0;
    for (int i = lo; i < hi; i++) s += deg[i];

    __shared__ int sm[1024];
    sm[t] = s;
    __syncthreads();
    for (int off = 1; off < 1024; off <<= 1) {
        int v = (t >= off) ? sm[t - off] : 0;
        __syncthreads();
        sm[t] += v;
        __syncthreads();
    }
    int base = (t > 0) ? sm[t - 1] : 0;
    for (int i = lo; i < hi; i++) {
        rs[i] = base;
        cur[i] = base;
        base += deg[i];
    }
}

// ---------------------------------------------------------------------
__global__ void fill_kernel(const int* __restrict__ src_ab, const int* __restrict__ dst_ab,
                            const int* __restrict__ src_ba, const int* __restrict__ dst_ba,
                            const int* __restrict__ src_aa, const int* __restrict__ dst_aa) {
    int i = blockIdx.x * blockDim.x + threadIdx.x;
    if (i >= EE) return;
    int p;
    p = atomicAdd(&g_cur_ab[dst_ab[i]], 1); g_csr_ab[p] = src_ab[i];
    p = atomicAdd(&g_cur_ba[dst_ba[i]], 1); g_csr_ba[p] = src_ba[i];
    p = atomicAdd(&g_cur_aa[dst_aa[i]], 1); g_csr_aa[p] = src_aa[i];
}

// ---------------------------------------------------------------------
// Tensor-core GEMM v2: H(fp16) = X(fp32->fp16) @ W(fp32->fp16), fp32 accum.
// BM=64, 128 threads = 4 warps; warp w owns rows 16w..16w+15.
// 57 KB smem -> 4 CTAs / 16 warps per SM. NA,NB are multiples of 16, so
// output guards are warp-granular (a warp's 16 rows are all-in or all-out).
// ---------------------------------------------------------------------
__global__ __launch_bounds__(128) void gemm_wmma_kernel(const float* __restrict__ X,
                                                        const float* __restrict__ W,
                                                        __half* __restrict__ H, int nrows) {
    extern __shared__ char smem[];
    __half* Ah = reinterpret_cast<__half*>(smem);                       // [64][AH_LD]
    __half* Wh = reinterpret_cast<__half*>(smem + SMEM_AH_BYTES);       // [128][WH_LD]
    float*  St = reinterpret_cast<float*>(smem + SMEM_AH_BYTES + SMEM_WH_BYTES); // [4][16*20]

    const int t = threadIdx.x;
    const int warp = t >> 5;
    const int lane = t & 31;
    const int row0 = blockIdx.x * 64;

    // A tile: 64 rows x 128 cols fp32 -> fp16 (2048 float4, 16/thread)
#pragma unroll 4
    for (int i = t; i < 64 * 32; i += 128) {
        int r = i >> 5;
        int c4 = (i & 31) * 4;
        float4 v = make_float4(0.f, 0.f, 0.f, 0.f);
        if (row0 + r < nrows)
            v = *reinterpret_cast<const float4*>(&X[(size_t)(row0 + r) * DIM + c4]);
        __half2 h0 = __floats2half2_rn(v.x, v.y);
        __half2 h1 = __floats2half2_rn(v.z, v.w);
        uint2 u = make_uint2(*reinterpret_cast<unsigned*>(&h0),
                             *reinterpret_cast<unsigned*>(&h1));
        *reinterpret_cast<uint2*>(&Ah[r * AH_LD + c4]) = u;
    }
    // W: 128 x 128 fp32 -> fp16 (4096 float4, 32/thread)
#pragma unroll 4
    for (int i = t; i < 128 * 32; i += 128) {
        int r = i >> 5;
        int c4 = (i & 31) * 4;
        float4 v = *reinterpret_cast<const float4*>(&W[(size_t)r * DIM + c4]);
        __half2 h0 = __floats2half2_rn(v.x, v.y);
        __half2 h1 = __floats2half2_rn(v.z, v.w);
        uint2 u = make_uint2(*reinterpret_cast<unsigned*>(&h0),
                             *reinterpret_cast<unsigned*>(&h1));
        *reinterpret_cast<uint2*>(&Wh[r * WH_LD + c4]) = u;
    }
    __syncthreads();

    wmma::fragment<wmma::accumulator, 16, 16, 16, float> acc[8];
#pragma unroll
    for (int n = 0; n < 8; n++) wmma::fill_fragment(acc[n], 0.f);

#pragma unroll
    for (int k = 0; k < 8; k++) {
        wmma::fragment<wmma::matrix_a, 16, 16, 16, __half, wmma::row_major> a;
        wmma::load_matrix_sync(a, &Ah[(warp * 16) * AH_LD + k * 16], AH_LD);
#pragma unroll
        for (int n = 0; n < 8; n++) {
            wmma::fragment<wmma::matrix_b, 16, 16, 16, __half, wmma::row_major> b;
            wmma::load_matrix_sync(b, &Wh[(k * 16) * WH_LD + n * 16], WH_LD);
            wmma::mma_sync(acc[n], a, b, acc[n]);
        }
    }

    // Epilogue: per-warp staging, fp32 -> fp16, uint4 stores.
    int grow0 = row0 + warp * 16;
    if (grow0 + 16 <= nrows) {    // nrows % 16 == 0 -> warp rows all valid or all invalid
        float* st = St + warp * (16 * 20);
#pragma unroll
        for (int n = 0; n < 8; n++) {
            wmma::store_matrix_sync(st, acc[n], 20, wmma::mem_row_major);
            __syncwarp();
            int r = lane >> 1;
            int c0 = (lane & 1) * 8;
            __half2 hp[4];
#pragma unroll
            for (int j = 0; j < 4; j++)
                hp[j] = __floats2half2_rn(st[r * 20 + c0 + 2 * j],
                                          st[r * 20 + c0 + 2 * j + 1]);
            uint4 u = make_uint4(*reinterpret_cast<unsigned*>(&hp[0]),
                                 *reinterpret_cast<unsigned*>(&hp[1]),
                                 *reinterpret_cast<unsigned*>(&hp[2]),
                                 *reinterpret_cast<unsigned*>(&hp[3]));
            *reinterpret_cast<uint4*>(&H[(size_t)(grow0 + r) * DIM + n * 16 + c0]) = u;
            __syncwarp();
        }
    }
}

// ---------------------------------------------------------------------
// Warp-per-node gather; fp16 h rows, fp32 accumulation.
// ---------------------------------------------------------------------
__device__ __forceinline__ float4 gather_accum(const int* __restrict__ csr,
                                               const int* __restrict__ deg_s,
                                               int start, int cnt,
                                               const __half* __restrict__ h, int lane) {
    float4 acc = make_float4(0.f, 0.f, 0.f, 0.f);
    int j = 0;
    while (j < cnt) {
        int m = min(32, cnt - j);
        int idx = 0;
        float inv = 0.f;
        if (lane < m) {
            idx = __ldcs(&csr[start + j + lane]);
            inv = rsqrtf((float)deg_s[idx]);
        }
#pragma unroll 4
        for (int k = 0; k < m; k++) {
            int s = __shfl_sync(0xffffffffu, idx, k);
            float iv = __shfl_sync(0xffffffffu, inv, k);
            uint2 u = *reinterpret_cast<const uint2*>(&h[(size_t)s * DIM + lane * 4]);
            __half2 p0 = *reinterpret_cast<__half2*>(&u.x);
            __half2 p1 = *reinterpret_cast<__half2*>(&u.y);
            float2 f0 = __half22float2(p0);
            float2 f1 = __half22float2(p1);
            acc.x += f0.x * iv; acc.y += f0.y * iv;
            acc.z += f1.x * iv; acc.w += f1.y * iv;
        }
        j += m;
    }
    return acc;
}

__global__ __launch_bounds__(256) void gather_a_kernel(float* __restrict__ out_a) {
    int gw = blockIdx.x * (blockDim.x >> 5) + (threadIdx.x >> 5);
    int lane = threadIdx.x & 31;
    if (gw >= NA) return;
    int d = gw;
    int c_ba = g_deg_t_ba[d];
    int c_aa = g_deg_t_aa[d];
    float4 s_ba = gather_accum(g_csr_ba, g_deg_s_ba, g_rs_ba[d], c_ba, g_h_ba, lane);
    float4 s_aa = gather_accum(g_csr_aa, g_deg_s_aa, g_rs_aa[d], c_aa, g_h_aa, lane);
    float rb = (c_ba > 0) ? rsqrtf((float)c_ba) * 0.5f : 0.f;
    float ra = (c_aa > 0) ? rsqrtf((float)c_aa) * 0.5f : 0.f;
    float4 v;
    v.x = fmaxf(s_ba.x * rb + s_aa.x * ra, 0.f);
    v.y = fmaxf(s_ba.y * rb + s_aa.y * ra, 0.f);
    v.z = fmaxf(s_ba.z * rb + s_aa.z * ra, 0.f);
    v.w = fmaxf(s_ba.w * rb + s_aa.w * ra, 0.f);
    __stcs(reinterpret_cast<float4*>(&out_a[(size_t)d * DIM + lane * 4]), v);
}

__global__ __launch_bounds__(256) void gather_b_kernel(float* __restrict__ out_b) {
    int gw = blockIdx.x * (blockDim.x >> 5) + (threadIdx.x >> 5);
    int lane = threadIdx.x & 31;
    if (gw >= NB) return;
    int d = gw;
    int c_ab = g_deg_t_ab[d];
    float4 s_ab = gather_accum(g_csr_ab, g_deg_s_ab, g_rs_ab[d], c_ab, g_h_ab, lane);
    float r = (c_ab > 0) ? rsqrtf((float)c_ab) : 0.f;
    float4 v;
    v.x = fmaxf(s_ab.x * r, 0.f);
    v.y = fmaxf(s_ab.y * r, 0.f);
    v.z = fmaxf(s_ab.z * r, 0.f);
    v.w = fmaxf(s_ab.w * r, 0.f);
    __stcs(reinterpret_cast<float4*>(&out_b[(size_t)d * DIM + lane * 4]), v);
}

// ---------------------------------------------------------------------
extern "C" void kernel_launch(void* const* d_in, const int* in_sizes, int n_in,
                              void* d_out, int out_size) {
    const float* x_a  = (const float*)d_in[0];
    const float* x_b  = (const float*)d_in[1];
    const float* W_ab = (const float*)d_in[2];
    const float* W_ba = (const float*)d_in[3];
    const float* W_aa = (const float*)d_in[4];
    const int* src_ab = (const int*)d_in[5];
    const int* dst_ab = (const int*)d_in[6];
    const int* src_ba = (const int*)d_in[7];
    const int* dst_ba = (const int*)d_in[8];
    const int* src_aa = (const int*)d_in[9];
    const int* dst_aa = (const int*)d_in[10];

    float* out   = (float*)d_out;
    float* out_a = out;                       // [NA,128]
    float* out_b = out + (size_t)NA * DIM;    // [NB,128]

    __half *h_ab, *h_ba, *h_aa;
    cudaGetSymbolAddress((void**)&h_ab, g_h_ab);
    cudaGetSymbolAddress((void**)&h_ba, g_h_ba);
    cudaGetSymbolAddress((void**)&h_aa, g_h_aa);

    // ---- fork: side stream runs the 3 GEMMs (no degree dependency) ----
    cudaEventRecord(g_evFork, 0);
    cudaStreamWaitEvent(g_s1, g_evFork, 0);

    gemm_wmma_kernel<<<(NB + 63) / 64, 128, GEMM_SMEM, g_s1>>>(x_b, W_ba, h_ba, NB);
    gemm_wmma_kernel<<<(NA + 63) / 64, 128, GEMM_SMEM, g_s1>>>(x_a, W_aa, h_aa, NA);
    cudaEventRecord(g_evGemmA, g_s1);                    // h_ba + h_aa ready
    gemm_wmma_kernel<<<(NA + 63) / 64, 128, GEMM_SMEM, g_s1>>>(x_a, W_ab, h_ab, NA);

    // ---- main stream: CSR build ----
    zero_kernel<<<512, 256>>>();
    degree_kernel<<<(EE + 255) / 256, 256>>>(src_ab, dst_ab, src_ba, dst_ba, src_aa, dst_aa);
    scan3_kernel<<<3, 1024>>>();
    fill_kernel<<<(EE + 255) / 256, 256>>>(src_ab, dst_ab, src_ba, dst_ba, src_aa, dst_aa);
    cudaEventRecord(g_evCsr, 0);                         // CSR + degrees ready

    // gather_a on main stream: needs CSR (in-stream) + h_ba/h_aa (event)
    cudaStreamWaitEvent(0, g_evGemmA, 0);
    gather_a_kernel<<<(NA + 7) / 8, 256>>>(out_a);

    // gather_b on side stream: needs h_ab (in-stream) + CSR (event)
    cudaStreamWaitEvent(g_s1, g_evCsr, 0);
    gather_b_kernel<<<(NB + 7) / 8, 256, 0, g_s1>>>(out_b);
    cudaEventRecord(g_evTailB, g_s1);

    // join
    cudaStreamWaitEvent(0, g_evTailB, 0);
}

// round 12
// speedup vs baseline: 1.1283x; 1.0494x over previous
#include <cuda_runtime.h>
#include <cuda_bf16.h>
#include <cuda_fp16.h>
#include <mma.h>

using namespace nvcuda;

#define NA 100000
#define NB 50000
#define DIM 128
#define EE 1000000

// ---- static device scratch ----
__device__ __half g_h_ab[(size_t)NA * DIM];   // x_a @ W_ab  -> out_b
__device__ __half g_h_ba[(size_t)NB * DIM];   // x_b @ W_ba  -> out_a
__device__ __half g_h_aa[(size_t)NA * DIM];   // x_a @ W_aa  -> out_a

__device__ int g_deg_s_ab[NA];
__device__ int g_deg_t_ab[NB];
__device__ int g_deg_s_ba[NB];
__device__ int g_deg_t_ba[NA];
__device__ int g_deg_s_aa[NA];
__device__ int g_deg_t_aa[NA];

// CSR-by-dst
__device__ int g_rs_ab[NB];
__device__ int g_rs_ba[NA];
__device__ int g_rs_aa[NA];
__device__ int g_cur_ab[NB];
__device__ int g_cur_ba[NA];
__device__ int g_cur_aa[NA];
__device__ int g_csr_ab[EE];
__device__ int g_csr_ba[EE];
__device__ int g_csr_aa[EE];

// ---- persistent GEMM smem layout ----
#define AH_LD 136
#define WH_LD 136
#define SMEM_AH   (64 * AH_LD * 2)               // 17408
#define SMEM_W1   (128 * WH_LD * 2)              // 34816 (per W)
#define SMEM_ST   (8 * 16 * 20 * 4)              // 10240
#define GEMM_SMEM (SMEM_AH + 3 * SMEM_W1 + SMEM_ST)   // 132096

#define NTB ((NB + 63) / 64)          // 782
#define NTA ((NA + 63) / 64)          // 1563
#define NTILES (NTB + NTA)            // 2345
#define GEMM_GRID 148

__global__ void gemm_all_kernel(const float* __restrict__ xa,
                                const float* __restrict__ xb,
                                const float* __restrict__ Wab,
                                const float* __restrict__ Wba,
                                const float* __restrict__ Waa);

// ---- streams/events for fork-join overlap ----
static cudaStream_t g_s1;
static cudaEvent_t g_evFork, g_evGemm, g_evCsr, g_evTailB;
static struct InitOnce {
    InitOnce() {
        cudaStreamCreateWithFlags(&g_s1, cudaStreamNonBlocking);
        cudaEventCreateWithFlags(&g_evFork, cudaEventDisableTiming);
        cudaEventCreateWithFlags(&g_evGemm, cudaEventDisableTiming);
        cudaEventCreateWithFlags(&g_evCsr, cudaEventDisableTiming);
        cudaEventCreateWithFlags(&g_evTailB, cudaEventDisableTiming);
        cudaFuncSetAttribute(gemm_all_kernel,
                             cudaFuncAttributeMaxDynamicSharedMemorySize, GEMM_SMEM);
    }
} g_initOnce;

// ---------------------------------------------------------------------
__global__ void zero_kernel() {
    int i = blockIdx.x * blockDim.x + threadIdx.x;
    int stride = gridDim.x * blockDim.x;
    for (int j = i; j < NA; j += stride) {
        g_deg_s_ab[j] = 0;
        g_deg_t_ba[j] = 0;
        g_deg_s_aa[j] = 0;
        g_deg_t_aa[j] = 0;
    }
    for (int j = i; j < NB; j += stride) {
        g_deg_t_ab[j] = 0;
        g_deg_s_ba[j] = 0;
    }
}

// ---------------------------------------------------------------------
__global__ void degree_kernel(const int* __restrict__ src_ab, const int* __restrict__ dst_ab,
                              const int* __restrict__ src_ba, const int* __restrict__ dst_ba,
                              const int* __restrict__ src_aa, const int* __restrict__ dst_aa) {
    int i = blockIdx.x * blockDim.x + threadIdx.x;
    if (i >= EE) return;
    atomicAdd(&g_deg_s_ab[src_ab[i]], 1);
    atomicAdd(&g_deg_t_ab[dst_ab[i]], 1);
    atomicAdd(&g_deg_s_ba[src_ba[i]], 1);
    atomicAdd(&g_deg_t_ba[dst_ba[i]], 1);
    atomicAdd(&g_deg_s_aa[src_aa[i]], 1);
    atomicAdd(&g_deg_t_aa[dst_aa[i]], 1);
}

// ---------------------------------------------------------------------
__global__ __launch_bounds__(1024) void scan3_kernel() {
    const int* deg;
    int n;
    int* rs;
    int* cur;
    if (blockIdx.x == 0)      { deg = g_deg_t_ab; n = NB; rs = g_rs_ab; cur = g_cur_ab; }
    else if (blockIdx.x == 1) { deg = g_deg_t_ba; n = NA; rs = g_rs_ba; cur = g_cur_ba; }
    else                      { deg = g_deg_t_aa; n = NA; rs = g_rs_aa; cur = g_cur_aa; }

    const int t = threadIdx.x;
    const int chunk = (n + 1023) >> 10;
    const int lo = t * chunk;
    const int hi = min(lo + chunk, n);

    int s = 0;
    for (int i = lo; i < hi; i++) s += deg[i];

    __shared__ int sm[1024];
    sm[t] = s;
    __syncthreads();
    for (int off = 1; off < 1024; off <<= 1) {
        int v = (t >= off) ? sm[t - off] : 0;
        __syncthreads();
        sm[t] += v;
        __syncthreads();
    }
    int base = (t > 0) ? sm[t - 1] : 0;
    for (int i = lo; i < hi; i++) {
        rs[i] = base;
        cur[i] = base;
        base += deg[i];
    }
}

// ---------------------------------------------------------------------
__global__ void fill_kernel(const int* __restrict__ src_ab, const int* __restrict__ dst_ab,
                            const int* __restrict__ src_ba, const int* __restrict__ dst_ba,
                            const int* __restrict__ src_aa, const int* __restrict__ dst_aa) {
    int i = blockIdx.x * blockDim.x + threadIdx.x;
    if (i >= EE) return;
    int p;
    p = atomicAdd(&g_cur_ab[dst_ab[i]], 1); g_csr_ab[p] = src_ab[i];
    p = atomicAdd(&g_cur_ba[dst_ba[i]], 1); g_csr_ba[p] = src_ba[i];
    p = atomicAdd(&g_cur_aa[dst_aa[i]], 1); g_csr_aa[p] = src_aa[i];
}

// ---------------------------------------------------------------------
// Persistent fused GEMM: all three H = X @ W products in one kernel.
// 148 blocks x 256 threads (8 warps). All three W's are converted to
// fp16 in smem ONCE per block; blocks stride over 2345 row-tiles.
// x_a tiles compute BOTH h_aa and h_ab from one A-tile load.
// Warp w: rows (w&3)*16..+16, N-half (w>>2)*64..+64 (4 wmma n-tiles).
// ---------------------------------------------------------------------
__global__ __launch_bounds__(256) void gemm_all_kernel(const float* __restrict__ xa,
                                                       const float* __restrict__ xb,
                                                       const float* __restrict__ Wab,
                                                       const float* __restrict__ Wba,
                                                       const float* __restrict__ Waa) {
    extern __shared__ char smem[];
    __half* Ah   = reinterpret_cast<__half*>(smem);                       // [64][AH_LD]
    __half* Wba_s = reinterpret_cast<__half*>(smem + SMEM_AH);            // [128][WH_LD]
    __half* Waa_s = reinterpret_cast<__half*>(smem + SMEM_AH + SMEM_W1);
    __half* Wab_s = reinterpret_cast<__half*>(smem + SMEM_AH + 2 * SMEM_W1);
    float*  St   = reinterpret_cast<float*>(smem + SMEM_AH + 3 * SMEM_W1); // [8][16*20]

    const int t = threadIdx.x;
    const int warp = t >> 5;
    const int lane = t & 31;
    const int wr = warp & 3;        // row group within tile
    const int wn = warp >> 2;       // N half (0 or 1)

    // Convert all three W's to fp16 smem once (4096 float4 each, 16/thread)
    {
        const float* Wsrc[3] = {Wba, Waa, Wab};
        __half* Wdst[3] = {Wba_s, Waa_s, Wab_s};
#pragma unroll
        for (int w = 0; w < 3; w++) {
#pragma unroll 4
            for (int i = t; i < 128 * 32; i += 256) {
                int r = i >> 5;
                int c4 = (i & 31) * 4;
                float4 v = *reinterpret_cast<const float4*>(&Wsrc[w][(size_t)r * DIM + c4]);
                __half2 h0 = __floats2half2_rn(v.x, v.y);
                __half2 h1 = __floats2half2_rn(v.z, v.w);
                uint2 u = make_uint2(*reinterpret_cast<unsigned*>(&h0),
                                     *reinterpret_cast<unsigned*>(&h1));
                *reinterpret_cast<uint2*>(&Wdst[w][r * WH_LD + c4]) = u;
            }
        }
    }

    float* st = St + warp * (16 * 20);

    for (int tile = blockIdx.x; tile < NTILES; tile += GEMM_GRID) {
        const float* X;
        int row0, nrows;
        bool dual;
        if (tile < NTB) { X = xb; row0 = tile * 64; nrows = NB; dual = false; }
        else            { X = xa; row0 = (tile - NTB) * 64; nrows = NA; dual = true; }

        __syncthreads();   // previous tile's mma reads of Ah done
        // A tile: 64 x 128 fp32 -> fp16 (2048 float4, 8/thread)
#pragma unroll
        for (int i = t; i < 64 * 32; i += 256) {
            int r = i >> 5;
            int c4 = (i & 31) * 4;
            float4 v = make_float4(0.f, 0.f, 0.f, 0.f);
            if (row0 + r < nrows)
                v = *reinterpret_cast<const float4*>(&X[(size_t)(row0 + r) * DIM + c4]);
            __half2 h0 = __floats2half2_rn(v.x, v.y);
            __half2 h1 = __floats2half2_rn(v.z, v.w);
            uint2 u = make_uint2(*reinterpret_cast<unsigned*>(&h0),
                                 *reinterpret_cast<unsigned*>(&h1));
            *reinterpret_cast<uint2*>(&Ah[r * AH_LD + c4]) = u;
        }
        __syncthreads();

        int grow0 = row0 + wr * 16;
        bool rowsValid = (grow0 + 16 <= nrows);   // nrows % 16 == 0

        for (int pass = 0; pass < (dual ? 2 : 1); pass++) {
            const __half* Wsm = dual ? (pass == 0 ? Waa_s : Wab_s) : Wba_s;
            __half* Hout = dual ? (pass == 0 ? g_h_aa : g_h_ab) : g_h_ba;

            wmma::fragment<wmma::accumulator, 16, 16, 16, float> acc[4];
#pragma unroll
            for (int n = 0; n < 4; n++) wmma::fill_fragment(acc[n], 0.f);

#pragma unroll
            for (int k = 0; k < 8; k++) {
                wmma::fragment<wmma::matrix_a, 16, 16, 16, __half, wmma::row_major> a;
                wmma::load_matrix_sync(a, &Ah[(wr * 16) * AH_LD + k * 16], AH_LD);
#pragma unroll
                for (int n = 0; n < 4; n++) {
                    wmma::fragment<wmma::matrix_b, 16, 16, 16, __half, wmma::row_major> b;
                    wmma::load_matrix_sync(b, &Wsm[(k * 16) * WH_LD + (wn * 4 + n) * 16], WH_LD);
                    wmma::mma_sync(acc[n], a, b, acc[n]);
                }
            }

            if (rowsValid) {
#pragma unroll
                for (int n = 0; n < 4; n++) {
                    wmma::store_matrix_sync(st, acc[n], 20, wmma::mem_row_major);
                    __syncwarp();
                    int r = lane >> 1;
                    int c0 = (lane & 1) * 8;
                    __half2 hp[4];
#pragma unroll
                    for (int j = 0; j < 4; j++)
                        hp[j] = __floats2half2_rn(st[r * 20 + c0 + 2 * j],
                                                  st[r * 20 + c0 + 2 * j + 1]);
                    uint4 u = make_uint4(*reinterpret_cast<unsigned*>(&hp[0]),
                                         *reinterpret_cast<unsigned*>(&hp[1]),
                                         *reinterpret_cast<unsigned*>(&hp[2]),
                                         *reinterpret_cast<unsigned*>(&hp[3]));
                    *reinterpret_cast<uint4*>(
                        &Hout[(size_t)(grow0 + r) * DIM + (wn * 4 + n) * 16 + c0]) = u;
                    __syncwarp();
                }
            }
        }
    }
}

// ---------------------------------------------------------------------
// Warp-per-node gather; fp16 h rows, fp32 accumulation.
// ---------------------------------------------------------------------
__device__ __forceinline__ float4 gather_accum(const int* __restrict__ csr,
                                               const int* __restrict__ deg_s,
                                               int start, int cnt,
                                               const __half* __restrict__ h, int lane) {
    float4 acc = make_float4(0.f, 0.f, 0.f, 0.f);
    int j = 0;
    while (j < cnt) {
        int m = min(32, cnt - j);
        int idx = 0;
        float inv = 0.f;
        if (lane < m) {
            idx = __ldcs(&csr[start + j + lane]);
            inv = rsqrtf((float)deg_s[idx]);
        }
#pragma unroll 4
        for (int k = 0; k < m; k++) {
            int s = __shfl_sync(0xffffffffu, idx, k);
            float iv = __shfl_sync(0xffffffffu, inv, k);
            uint2 u = *reinterpret_cast<const uint2*>(&h[(size_t)s * DIM + lane * 4]);
            __half2 p0 = *reinterpret_cast<__half2*>(&u.x);
            __half2 p1 = *reinterpret_cast<__half2*>(&u.y);
            float2 f0 = __half22float2(p0);
            float2 f1 = __half22float2(p1);
            acc.x += f0.x * iv; acc.y += f0.y * iv;
            acc.z += f1.x * iv; acc.w += f1.y * iv;
        }
        j += m;
    }
    return acc;
}

__global__ __launch_bounds__(256) void gather_a_kernel(float* __restrict__ out_a) {
    int gw = blockIdx.x * (blockDim.x >> 5) + (threadIdx.x >> 5);
    int lane = threadIdx.x & 31;
    if (gw >= NA) return;
    int d = gw;
    int c_ba = g_deg_t_ba[d];
    int c_aa = g_deg_t_aa[d];
    float4 s_ba = gather_accum(g_csr_ba, g_deg_s_ba, g_rs_ba[d], c_ba, g_h_ba, lane);
    float4 s_aa = gather_accum(g_csr_aa, g_deg_s_aa, g_rs_aa[d], c_aa, g_h_aa, lane);
    float rb = (c_ba > 0) ? rsqrtf((float)c_ba) * 0.5f : 0.f;
    float ra = (c_aa > 0) ? rsqrtf((float)c_aa) * 0.5f : 0.f;
    float4 v;
    v.x = fmaxf(s_ba.x * rb + s_aa.x * ra, 0.f);
    v.y = fmaxf(s_ba.y * rb + s_aa.y * ra, 0.f);
    v.z = fmaxf(s_ba.z * rb + s_aa.z * ra, 0.f);
    v.w = fmaxf(s_ba.w * rb + s_aa.w * ra, 0.f);
    __stcs(reinterpret_cast<float4*>(&out_a[(size_t)d * DIM + lane * 4]), v);
}

__global__ __launch_bounds__(256) void gather_b_kernel(float* __restrict__ out_b) {
    int gw = blockIdx.x * (blockDim.x >> 5) + (threadIdx.x >> 5);
    int lane = threadIdx.x & 31;
    if (gw >= NB) return;
    int d = gw;
    int c_ab = g_deg_t_ab[d];
    float4 s_ab = gather_accum(g_csr_ab, g_deg_s_ab, g_rs_ab[d], c_ab, g_h_ab, lane);
    float r = (c_ab > 0) ? rsqrtf((float)c_ab) : 0.f;
    float4 v;
    v.x = fmaxf(s_ab.x * r, 0.f);
    v.y = fmaxf(s_ab.y * r, 0.f);
    v.z = fmaxf(s_ab.z * r, 0.f);
    v.w = fmaxf(s_ab.w * r, 0.f);
    __stcs(reinterpret_cast<float4*>(&out_b[(size_t)d * DIM + lane * 4]), v);
}

// ---------------------------------------------------------------------
extern "C" void kernel_launch(void* const* d_in, const int* in_sizes, int n_in,
                              void* d_out, int out_size) {
    const float* x_a  = (const float*)d_in[0];
    const float* x_b  = (const float*)d_in[1];
    const float* W_ab = (const float*)d_in[2];
    const float* W_ba = (const float*)d_in[3];
    const float* W_aa = (const float*)d_in[4];
    const int* src_ab = (const int*)d_in[5];
    const int* dst_ab = (const int*)d_in[6];
    const int* src_ba = (const int*)d_in[7];
    const int* dst_ba = (const int*)d_in[8];
    const int* src_aa = (const int*)d_in[9];
    const int* dst_aa = (const int*)d_in[10];

    float* out   = (float*)d_out;
    float* out_a = out;                       // [NA,128]
    float* out_b = out + (size_t)NA * DIM;    // [NB,128]

    // ---- fork: side stream runs the fused persistent GEMM ----
    cudaEventRecord(g_evFork, 0);
    cudaStreamWaitEvent(g_s1, g_evFork, 0);

    gemm_all_kernel<<<GEMM_GRID, 256, GEMM_SMEM, g_s1>>>(x_a, x_b, W_ab, W_ba, W_aa);
    cudaEventRecord(g_evGemm, g_s1);

    // ---- main stream: CSR build ----
    zero_kernel<<<512, 256>>>();
    degree_kernel<<<(EE + 255) / 256, 256>>>(src_ab, dst_ab, src_ba, dst_ba, src_aa, dst_aa);
    scan3_kernel<<<3, 1024>>>();
    fill_kernel<<<(EE + 255) / 256, 256>>>(src_ab, dst_ab, src_ba, dst_ba, src_aa, dst_aa);
    cudaEventRecord(g_evCsr, 0);

    // gather_a on main: CSR in-stream + h via event
    cudaStreamWaitEvent(0, g_evGemm, 0);
    gather_a_kernel<<<(NA + 7) / 8, 256>>>(out_a);

    // gather_b on side: h in-stream + CSR via event
    cudaStreamWaitEvent(g_s1, g_evCsr, 0);
    gather_b_kernel<<<(NB + 7) / 8, 256, 0, g_s1>>>(out_b);
    cudaEventRecord(g_evTailB, g_s1);

    // join
    cudaStreamWaitEvent(0, g_evTailB, 0);
}

// round 13
// speedup vs baseline: 1.7759x; 1.5739x over previous
#include <cuda_runtime.h>
#include <cuda_bf16.h>
#include <cuda_fp16.h>
#include <mma.h>

using namespace nvcuda;

#define NA 100000
#define NB 50000
#define DIM 128
#define EE 1000000

// ---- static device scratch ----
__device__ __half g_h_ab[(size_t)NA * DIM];   // x_a @ W_ab  -> out_b
__device__ __half g_h_ba[(size_t)NB * DIM];   // x_b @ W_ba  -> out_a
__device__ __half g_h_aa[(size_t)NA * DIM];   // x_a @ W_aa  -> out_a

__device__ int g_deg_s_ab[NA];
__device__ int g_deg_t_ab[NB];
__device__ int g_deg_s_ba[NB];
__device__ int g_deg_t_ba[NA];
__device__ int g_deg_s_aa[NA];
__device__ int g_deg_t_aa[NA];

// CSR-by-dst
__device__ int g_rs_ab[NB];
__device__ int g_rs_ba[NA];
__device__ int g_rs_aa[NA];
__device__ int g_cur_ab[NB];
__device__ int g_cur_ba[NA];
__device__ int g_cur_aa[NA];
__device__ int g_csr_ab[EE];
__device__ int g_csr_ba[EE];
__device__ int g_csr_aa[EE];

// scan partials: array a at offset a*128
__device__ int g_part[3 * 128];

// ---- scan chunking ----
#define CHUNK 1024
#define NCH_AB ((NB + CHUNK - 1) / CHUNK)     // 49
#define NCH_BA ((NA + CHUNK - 1) / CHUNK)     // 98
#define NCH_AA ((NA + CHUNK - 1) / CHUNK)     // 98
#define NCH_TOT (NCH_AB + NCH_BA + NCH_AA)    // 245

// ---- persistent GEMM smem layout ----
#define AH_LD 136
#define WH_LD 136
#define SMEM_AH   (64 * AH_LD * 2)               // 17408
#define SMEM_W1   (128 * WH_LD * 2)              // 34816 (per W)
#define SMEM_ST   (8 * 16 * 20 * 4)              // 10240
#define GEMM_SMEM (SMEM_AH + 3 * SMEM_W1 + SMEM_ST)   // 132096

#define NTB ((NB + 63) / 64)          // 782
#define NTA ((NA + 63) / 64)          // 1563
#define NTILES (NTB + NTA)            // 2345
#define GEMM_GRID 148

__global__ void gemm_all_kernel(const float* __restrict__ xa,
                                const float* __restrict__ xb,
                                const float* __restrict__ Wab,
                                const float* __restrict__ Wba,
                                const float* __restrict__ Waa);

// ---- streams/events for fork-join overlap ----
static cudaStream_t g_s1;
static cudaEvent_t g_evFork, g_evGemm, g_evCsr, g_evTailB;
static struct InitOnce {
    InitOnce() {
        cudaStreamCreateWithFlags(&g_s1, cudaStreamNonBlocking);
        cudaEventCreateWithFlags(&g_evFork, cudaEventDisableTiming);
        cudaEventCreateWithFlags(&g_evGemm, cudaEventDisableTiming);
        cudaEventCreateWithFlags(&g_evCsr, cudaEventDisableTiming);
        cudaEventCreateWithFlags(&g_evTailB, cudaEventDisableTiming);
        cudaFuncSetAttribute(gemm_all_kernel,
                             cudaFuncAttributeMaxDynamicSharedMemorySize, GEMM_SMEM);
    }
} g_initOnce;

// ---------------------------------------------------------------------
__global__ void zero_kernel() {
    int i = blockIdx.x * blockDim.x + threadIdx.x;
    int stride = gridDim.x * blockDim.x;
    for (int j = i; j < NA; j += stride) {
        g_deg_s_ab[j] = 0;
        g_deg_t_ba[j] = 0;
        g_deg_s_aa[j] = 0;
        g_deg_t_aa[j] = 0;
    }
    for (int j = i; j < NB; j += stride) {
        g_deg_t_ab[j] = 0;
        g_deg_s_ba[j] = 0;
    }
}

// ---------------------------------------------------------------------
__global__ void degree_kernel(const int* __restrict__ src_ab, const int* __restrict__ dst_ab,
                              const int* __restrict__ src_ba, const int* __restrict__ dst_ba,
                              const int* __restrict__ src_aa, const int* __restrict__ dst_aa) {
    int i = blockIdx.x * blockDim.x + threadIdx.x;
    if (i >= EE) return;
    atomicAdd(&g_deg_s_ab[src_ab[i]], 1);
    atomicAdd(&g_deg_t_ab[dst_ab[i]], 1);
    atomicAdd(&g_deg_s_ba[src_ba[i]], 1);
    atomicAdd(&g_deg_t_ba[dst_ba[i]], 1);
    atomicAdd(&g_deg_s_aa[src_aa[i]], 1);
    atomicAdd(&g_deg_t_aa[dst_aa[i]], 1);
}

// ---------------------------------------------------------------------
// Parallel scan, phase 1: per-chunk block reduce -> g_part
// ---------------------------------------------------------------------
__device__ __forceinline__ void scan_map(int b, const int*& deg, int& n,
                                         int& chunk, int& pbase,
                                         int*& rs, int*& cur) {
    if (b < NCH_AB) {
        deg = g_deg_t_ab; n = NB; chunk = b; pbase = 0;
        rs = g_rs_ab; cur = g_cur_ab;
    } else if (b < NCH_AB + NCH_BA) {
        deg = g_deg_t_ba; n = NA; chunk = b - NCH_AB; pbase = 128;
        rs = g_rs_ba; cur = g_cur_ba;
    } else {
        deg = g_deg_t_aa; n = NA; chunk = b - NCH_AB - NCH_BA; pbase = 256;
        rs = g_rs_aa; cur = g_cur_aa;
    }
}

__global__ __launch_bounds__(256) void scan_p1_kernel() {
    const int* deg; int n, chunk, pbase; int *rs, *cur;
    scan_map(blockIdx.x, deg, n, chunk, pbase, rs, cur);
    int t = threadIdx.x;
    int lo = chunk * CHUNK;
    int s = 0;
#pragma unroll
    for (int i = 0; i < 4; i++) {
        int idx = lo + t * 4 + i;
        if (idx < n) s += deg[idx];
    }
    __shared__ int sm[256];
    sm[t] = s;
    __syncthreads();
#pragma unroll
    for (int off = 128; off > 0; off >>= 1) {
        if (t < off) sm[t] += sm[t + off];
        __syncthreads();
    }
    if (t == 0) g_part[pbase + chunk] = sm[0];
}

// phase 2: exclusive scan of partials (one block per array)
__global__ __launch_bounds__(128) void scan_p2_kernel() {
    int a = blockIdx.x;
    int base = a * 128;
    int cnt = (a == 0) ? NCH_AB : ((a == 1) ? NCH_BA : NCH_AA);
    int t = threadIdx.x;
    int v = (t < cnt) ? g_part[base + t] : 0;
    __shared__ int sm[128];
    sm[t] = v;
    __syncthreads();
#pragma unroll
    for (int off = 1; off < 128; off <<= 1) {
        int u = (t >= off) ? sm[t - off] : 0;
        __syncthreads();
        sm[t] += u;
        __syncthreads();
    }
    if (t < cnt) g_part[base + t] = sm[t] - v;   // exclusive
}

// phase 3: per-chunk exclusive scan + offset -> rs/cur
__global__ __launch_bounds__(256) void scan_p3_kernel() {
    const int* deg; int n, chunk, pbase; int *rs, *cur;
    scan_map(blockIdx.x, deg, n, chunk, pbase, rs, cur);
    int t = threadIdx.x;
    int lo = chunk * CHUNK;
    int vals[4];
    int s = 0;
#pragma unroll
    for (int i = 0; i < 4; i++) {
        int idx = lo + t * 4 + i;
        vals[i] = (idx < n) ? deg[idx] : 0;
        s += vals[i];
    }
    __shared__ int sm[256];
    sm[t] = s;
    __syncthreads();
#pragma unroll
    for (int off = 1; off < 256; off <<= 1) {
        int u = (t >= off) ? sm[t - off] : 0;
        __syncthreads();
        sm[t] += u;
        __syncthreads();
    }
    int off0 = g_part[pbase + chunk] + sm[t] - s;   // exclusive within array
#pragma unroll
    for (int i = 0; i < 4; i++) {
        int idx = lo + t * 4 + i;
        if (idx < n) {
            rs[idx] = off0;
            cur[idx] = off0;
            off0 += vals[i];
        }
    }
}

// ---------------------------------------------------------------------
__global__ void fill_kernel(const int* __restrict__ src_ab, const int* __restrict__ dst_ab,
                            const int* __restrict__ src_ba, const int* __restrict__ dst_ba,
                            const int* __restrict__ src_aa, const int* __restrict__ dst_aa) {
    int i = blockIdx.x * blockDim.x + threadIdx.x;
    if (i >= EE) return;
    int p;
    p = atomicAdd(&g_cur_ab[dst_ab[i]], 1); g_csr_ab[p] = src_ab[i];
    p = atomicAdd(&g_cur_ba[dst_ba[i]], 1); g_csr_ba[p] = src_ba[i];
    p = atomicAdd(&g_cur_aa[dst_aa[i]], 1); g_csr_aa[p] = src_aa[i];
}

// ---------------------------------------------------------------------
// Persistent fused GEMM (unchanged from R12)
// ---------------------------------------------------------------------
__global__ __launch_bounds__(256) void gemm_all_kernel(const float* __restrict__ xa,
                                                       const float* __restrict__ xb,
                                                       const float* __restrict__ Wab,
                                                       const float* __restrict__ Wba,
                                                       const float* __restrict__ Waa) {
    extern __shared__ char smem[];
    __half* Ah    = reinterpret_cast<__half*>(smem);                       // [64][AH_LD]
    __half* Wba_s = reinterpret_cast<__half*>(smem + SMEM_AH);             // [128][WH_LD]
    __half* Waa_s = reinterpret_cast<__half*>(smem + SMEM_AH + SMEM_W1);
    __half* Wab_s = reinterpret_cast<__half*>(smem + SMEM_AH + 2 * SMEM_W1);
    float*  St    = reinterpret_cast<float*>(smem + SMEM_AH + 3 * SMEM_W1); // [8][16*20]

    const int t = threadIdx.x;
    const int warp = t >> 5;
    const int lane = t & 31;
    const int wr = warp & 3;
    const int wn = warp >> 2;

    {
        const float* Wsrc[3] = {Wba, Waa, Wab};
        __half* Wdst[3] = {Wba_s, Waa_s, Wab_s};
#pragma unroll
        for (int w = 0; w < 3; w++) {
#pragma unroll 4
            for (int i = t; i < 128 * 32; i += 256) {
                int r = i >> 5;
                int c4 = (i & 31) * 4;
                float4 v = *reinterpret_cast<const float4*>(&Wsrc[w][(size_t)r * DIM + c4]);
                __half2 h0 = __floats2half2_rn(v.x, v.y);
                __half2 h1 = __floats2half2_rn(v.z, v.w);
                uint2 u = make_uint2(*reinterpret_cast<unsigned*>(&h0),
                                     *reinterpret_cast<unsigned*>(&h1));
                *reinterpret_cast<uint2*>(&Wdst[w][r * WH_LD + c4]) = u;
            }
        }
    }

    float* st = St + warp * (16 * 20);

    for (int tile = blockIdx.x; tile < NTILES; tile += GEMM_GRID) {
        const float* X;
        int row0, nrows;
        bool dual;
        if (tile < NTB) { X = xb; row0 = tile * 64; nrows = NB; dual = false; }
        else            { X = xa; row0 = (tile - NTB) * 64; nrows = NA; dual = true; }

        __syncthreads();
#pragma unroll
        for (int i = t; i < 64 * 32; i += 256) {
            int r = i >> 5;
            int c4 = (i & 31) * 4;
            float4 v = make_float4(0.f, 0.f, 0.f, 0.f);
            if (row0 + r < nrows)
                v = *reinterpret_cast<const float4*>(&X[(size_t)(row0 + r) * DIM + c4]);
            __half2 h0 = __floats2half2_rn(v.x, v.y);
            __half2 h1 = __floats2half2_rn(v.z, v.w);
            uint2 u = make_uint2(*reinterpret_cast<unsigned*>(&h0),
                                 *reinterpret_cast<unsigned*>(&h1));
            *reinterpret_cast<uint2*>(&Ah[r * AH_LD + c4]) = u;
        }
        __syncthreads();

        int grow0 = row0 + wr * 16;
        bool rowsValid = (grow0 + 16 <= nrows);

        for (int pass = 0; pass < (dual ? 2 : 1); pass++) {
            const __half* Wsm = dual ? (pass == 0 ? Waa_s : Wab_s) : Wba_s;
            __half* Hout = dual ? (pass == 0 ? g_h_aa : g_h_ab) : g_h_ba;

            wmma::fragment<wmma::accumulator, 16, 16, 16, float> acc[4];
#pragma unroll
            for (int n = 0; n < 4; n++) wmma::fill_fragment(acc[n], 0.f);

#pragma unroll
            for (int k = 0; k < 8; k++) {
                wmma::fragment<wmma::matrix_a, 16, 16, 16, __half, wmma::row_major> a;
                wmma::load_matrix_sync(a, &Ah[(wr * 16) * AH_LD + k * 16], AH_LD);
#pragma unroll
                for (int n = 0; n < 4; n++) {
                    wmma::fragment<wmma::matrix_b, 16, 16, 16, __half, wmma::row_major> b;
                    wmma::load_matrix_sync(b, &Wsm[(k * 16) * WH_LD + (wn * 4 + n) * 16], WH_LD);
                    wmma::mma_sync(acc[n], a, b, acc[n]);
                }
            }

            if (rowsValid) {
#pragma unroll
                for (int n = 0; n < 4; n++) {
                    wmma::store_matrix_sync(st, acc[n], 20, wmma::mem_row_major);
                    __syncwarp();
                    int r = lane >> 1;
                    int c0 = (lane & 1) * 8;
                    __half2 hp[4];
#pragma unroll
                    for (int j = 0; j < 4; j++)
                        hp[j] = __floats2half2_rn(st[r * 20 + c0 + 2 * j],
                                                  st[r * 20 + c0 + 2 * j + 1]);
                    uint4 u = make_uint4(*reinterpret_cast<unsigned*>(&hp[0]),
                                         *reinterpret_cast<unsigned*>(&hp[1]),
                                         *reinterpret_cast<unsigned*>(&hp[2]),
                                         *reinterpret_cast<unsigned*>(&hp[3]));
                    *reinterpret_cast<uint4*>(
                        &Hout[(size_t)(grow0 + r) * DIM + (wn * 4 + n) * 16 + c0]) = u;
                    __syncwarp();
                }
            }
        }
    }
}

// ---------------------------------------------------------------------
// Warp-per-node gather; fp16 h rows, fp32 accumulation.
// ---------------------------------------------------------------------
__device__ __forceinline__ float4 gather_accum(const int* __restrict__ csr,
                                               const int* __restrict__ deg_s,
                                               int start, int cnt,
                                               const __half* __restrict__ h, int lane) {
    float4 acc = make_float4(0.f, 0.f, 0.f, 0.f);
    int j = 0;
    while (j < cnt) {
        int m = min(32, cnt - j);
        int idx = 0;
        float inv = 0.f;
        if (lane < m) {
            idx = __ldcs(&csr[start + j + lane]);
            inv = rsqrtf((float)deg_s[idx]);
        }
#pragma unroll 4
        for (int k = 0; k < m; k++) {
            int s = __shfl_sync(0xffffffffu, idx, k);
            float iv = __shfl_sync(0xffffffffu, inv, k);
            uint2 u = *reinterpret_cast<const uint2*>(&h[(size_t)s * DIM + lane * 4]);
            __half2 p0 = *reinterpret_cast<__half2*>(&u.x);
            __half2 p1 = *reinterpret_cast<__half2*>(&u.y);
            float2 f0 = __half22float2(p0);
            float2 f1 = __half22float2(p1);
            acc.x += f0.x * iv; acc.y += f0.y * iv;
            acc.z += f1.x * iv; acc.w += f1.y * iv;
        }
        j += m;
    }
    return acc;
}

__global__ __launch_bounds__(256) void gather_a_kernel(float* __restrict__ out_a) {
    int gw = blockIdx.x * (blockDim.x >> 5) + (threadIdx.x >> 5);
    int lane = threadIdx.x & 31;
    if (gw >= NA) return;
    int d = gw;
    int c_ba = g_deg_t_ba[d];
    int c_aa = g_deg_t_aa[d];
    float4 s_ba = gather_accum(g_csr_ba, g_deg_s_ba, g_rs_ba[d], c_ba, g_h_ba, lane);
    float4 s_aa = gather_accum(g_csr_aa, g_deg_s_aa, g_rs_aa[d], c_aa, g_h_aa, lane);
    float rb = (c_ba > 0) ? rsqrtf((float)c_ba) * 0.5f : 0.f;
    float ra = (c_aa > 0) ? rsqrtf((float)c_aa) * 0.5f : 0.f;
    float4 v;
    v.x = fmaxf(s_ba.x * rb + s_aa.x * ra, 0.f);
    v.y = fmaxf(s_ba.y * rb + s_aa.y * ra, 0.f);
    v.z = fmaxf(s_ba.z * rb + s_aa.z * ra, 0.f);
    v.w = fmaxf(s_ba.w * rb + s_aa.w * ra, 0.f);
    __stcs(reinterpret_cast<float4*>(&out_a[(size_t)d * DIM + lane * 4]), v);
}

__global__ __launch_bounds__(256) void gather_b_kernel(float* __restrict__ out_b) {
    int gw = blockIdx.x * (blockDim.x >> 5) + (threadIdx.x >> 5);
    int lane = threadIdx.x & 31;
    if (gw >= NB) return;
    int d = gw;
    int c_ab = g_deg_t_ab[d];
    float4 s_ab = gather_accum(g_csr_ab, g_deg_s_ab, g_rs_ab[d], c_ab, g_h_ab, lane);
    float r = (c_ab > 0) ? rsqrtf((float)c_ab) : 0.f;
    float4 v;
    v.x = fmaxf(s_ab.x * r, 0.f);
    v.y = fmaxf(s_ab.y * r, 0.f);
    v.z = fmaxf(s_ab.z * r, 0.f);
    v.w = fmaxf(s_ab.w * r, 0.f);
    __stcs(reinterpret_cast<float4*>(&out_b[(size_t)d * DIM + lane * 4]), v);
}

// ---------------------------------------------------------------------
extern "C" void kernel_launch(void* const* d_in, const int* in_sizes, int n_in,
                              void* d_out, int out_size) {
    const float* x_a  = (const float*)d_in[0];
    const float* x_b  = (const float*)d_in[1];
    const float* W_ab = (const float*)d_in[2];
    const float* W_ba = (const float*)d_in[3];
    const float* W_aa = (const float*)d_in[4];
    const int* src_ab = (const int*)d_in[5];
    const int* dst_ab = (const int*)d_in[6];
    const int* src_ba = (const int*)d_in[7];
    const int* dst_ba = (const int*)d_in[8];
    const int* src_aa = (const int*)d_in[9];
    const int* dst_aa = (const int*)d_in[10];

    float* out   = (float*)d_out;
    float* out_a = out;                       // [NA,128]
    float* out_b = out + (size_t)NA * DIM;    // [NB,128]

    // ---- fork: side stream runs the fused persistent GEMM ----
    cudaEventRecord(g_evFork, 0);
    cudaStreamWaitEvent(g_s1, g_evFork, 0);

    gemm_all_kernel<<<GEMM_GRID, 256, GEMM_SMEM, g_s1>>>(x_a, x_b, W_ab, W_ba, W_aa);
    cudaEventRecord(g_evGemm, g_s1);

    // ---- main stream: CSR build ----
    zero_kernel<<<512, 256>>>();
    degree_kernel<<<(EE + 255) / 256, 256>>>(src_ab, dst_ab, src_ba, dst_ba, src_aa, dst_aa);
    scan_p1_kernel<<<NCH_TOT, 256>>>();
    scan_p2_kernel<<<3, 128>>>();
    scan_p3_kernel<<<NCH_TOT, 256>>>();
    fill_kernel<<<(EE + 255) / 256, 256>>>(src_ab, dst_ab, src_ba, dst_ba, src_aa, dst_aa);
    cudaEventRecord(g_evCsr, 0);

    // gather_a on main: CSR in-stream + h via event
    cudaStreamWaitEvent(0, g_evGemm, 0);
    gather_a_kernel<<<(NA + 7) / 8, 256>>>(out_a);

    // gather_b on side: h in-stream + CSR via event
    cudaStreamWaitEvent(g_s1, g_evCsr, 0);
    gather_b_kernel<<<(NB + 7) / 8, 256, 0, g_s1>>>(out_b);
    cudaEventRecord(g_evTailB, g_s1);

    // join
    cudaStreamWaitEvent(0, g_evTailB, 0);
}

// round 14
// speedup vs baseline: 1.8325x; 1.0319x over previous
#include <cuda_runtime.h>
#include <cuda_bf16.h>
#include <cuda_fp16.h>
#include <mma.h>

using namespace nvcuda;

#define NA 100000
#define NB 50000
#define DIM 128
#define EE 1000000

// ---- static device scratch ----
__device__ __half g_h_ab[(size_t)NA * DIM];   // x_a @ W_ab  -> out_b
__device__ __half g_h_ba[(size_t)NB * DIM];   // x_b @ W_ba  -> out_a
__device__ __half g_h_aa[(size_t)NA * DIM];   // x_a @ W_aa  -> out_a

__device__ int g_deg_s_ab[NA];
__device__ int g_deg_t_ab[NB];
__device__ int g_deg_s_ba[NB];
__device__ int g_deg_t_ba[NA];
__device__ int g_deg_s_aa[NA];
__device__ int g_deg_t_aa[NA];

// CSR-by-dst
__device__ int g_rs_ab[NB];
__device__ int g_rs_ba[NA];
__device__ int g_rs_aa[NA];
__device__ int g_cur_ab[NB];
__device__ int g_cur_ba[NA];
__device__ int g_cur_aa[NA];
__device__ int g_csr_ab[EE];
__device__ int g_csr_ba[EE];
__device__ int g_csr_aa[EE];

// scan partials: array a at offset a*128
__device__ int g_part[3 * 128];

// ---- scan chunking ----
#define CHUNK 1024
#define NCH_AB ((NB + CHUNK - 1) / CHUNK)     // 49
#define NCH_BA ((NA + CHUNK - 1) / CHUNK)     // 98
#define NCH_AA ((NA + CHUNK - 1) / CHUNK)     // 98
#define NCH_TOT (NCH_AB + NCH_BA + NCH_AA)    // 245

// ---- persistent GEMM smem layout ----
#define AH_LD 136
#define WH_LD 136
#define SMEM_AH   (64 * AH_LD * 2)               // 17408
#define SMEM_W1   (128 * WH_LD * 2)              // 34816 (per W)
#define SMEM_ST   (8 * 16 * 20 * 4)              // 10240
#define GEMM_SMEM (SMEM_AH + 3 * SMEM_W1 + SMEM_ST)   // 132096

#define NTB ((NB + 63) / 64)          // 782
#define NTA ((NA + 63) / 64)          // 1563
#define NTILES (NTB + NTA)            // 2345
#define GEMM_GRID 148

__global__ void gemm_all_kernel(const float* __restrict__ xa,
                                const float* __restrict__ xb,
                                const float* __restrict__ Wab,
                                const float* __restrict__ Wba,
                                const float* __restrict__ Waa);

// ---- streams/events for fork-join overlap ----
static cudaStream_t g_s1;
static cudaEvent_t g_evFork, g_evGemm, g_evScan, g_evTailB;
static struct InitOnce {
    InitOnce() {
        cudaStreamCreateWithFlags(&g_s1, cudaStreamNonBlocking);
        cudaEventCreateWithFlags(&g_evFork, cudaEventDisableTiming);
        cudaEventCreateWithFlags(&g_evGemm, cudaEventDisableTiming);
        cudaEventCreateWithFlags(&g_evScan, cudaEventDisableTiming);
        cudaEventCreateWithFlags(&g_evTailB, cudaEventDisableTiming);
        cudaFuncSetAttribute(gemm_all_kernel,
                             cudaFuncAttributeMaxDynamicSharedMemorySize, GEMM_SMEM);
    }
} g_initOnce;

// ---------------------------------------------------------------------
__global__ void zero_kernel() {
    int i = blockIdx.x * blockDim.x + threadIdx.x;
    int stride = gridDim.x * blockDim.x;
    for (int j = i; j < NA; j += stride) {
        g_deg_s_ab[j] = 0;
        g_deg_t_ba[j] = 0;
        g_deg_s_aa[j] = 0;
        g_deg_t_aa[j] = 0;
    }
    for (int j = i; j < NB; j += stride) {
        g_deg_t_ab[j] = 0;
        g_deg_s_ba[j] = 0;
    }
}

// ---------------------------------------------------------------------
// dst-degree histograms only (src degrees folded into the fill kernels)
// ---------------------------------------------------------------------
__global__ void degree_dst_kernel(const int* __restrict__ dst_ab,
                                  const int* __restrict__ dst_ba,
                                  const int* __restrict__ dst_aa) {
    int i = blockIdx.x * blockDim.x + threadIdx.x;
    if (i >= EE) return;
    atomicAdd(&g_deg_t_ab[dst_ab[i]], 1);
    atomicAdd(&g_deg_t_ba[dst_ba[i]], 1);
    atomicAdd(&g_deg_t_aa[dst_aa[i]], 1);
}

// ---------------------------------------------------------------------
// Parallel scan (3 phases)
// ---------------------------------------------------------------------
__device__ __forceinline__ void scan_map(int b, const int*& deg, int& n,
                                         int& chunk, int& pbase,
                                         int*& rs, int*& cur) {
    if (b < NCH_AB) {
        deg = g_deg_t_ab; n = NB; chunk = b; pbase = 0;
        rs = g_rs_ab; cur = g_cur_ab;
    } else if (b < NCH_AB + NCH_BA) {
        deg = g_deg_t_ba; n = NA; chunk = b - NCH_AB; pbase = 128;
        rs = g_rs_ba; cur = g_cur_ba;
    } else {
        deg = g_deg_t_aa; n = NA; chunk = b - NCH_AB - NCH_BA; pbase = 256;
        rs = g_rs_aa; cur = g_cur_aa;
    }
}

__global__ __launch_bounds__(256) void scan_p1_kernel() {
    const int* deg; int n, chunk, pbase; int *rs, *cur;
    scan_map(blockIdx.x, deg, n, chunk, pbase, rs, cur);
    int t = threadIdx.x;
    int lo = chunk * CHUNK;
    int s = 0;
#pragma unroll
    for (int i = 0; i < 4; i++) {
        int idx = lo + t * 4 + i;
        if (idx < n) s += deg[idx];
    }
    __shared__ int sm[256];
    sm[t] = s;
    __syncthreads();
#pragma unroll
    for (int off = 128; off > 0; off >>= 1) {
        if (t < off) sm[t] += sm[t + off];
        __syncthreads();
    }
    if (t == 0) g_part[pbase + chunk] = sm[0];
}

__global__ __launch_bounds__(128) void scan_p2_kernel() {
    int a = blockIdx.x;
    int base = a * 128;
    int cnt = (a == 0) ? NCH_AB : ((a == 1) ? NCH_BA : NCH_AA);
    int t = threadIdx.x;
    int v = (t < cnt) ? g_part[base + t] : 0;
    __shared__ int sm[128];
    sm[t] = v;
    __syncthreads();
#pragma unroll
    for (int off = 1; off < 128; off <<= 1) {
        int u = (t >= off) ? sm[t - off] : 0;
        __syncthreads();
        sm[t] += u;
        __syncthreads();
    }
    if (t < cnt) g_part[base + t] = sm[t] - v;   // exclusive
}

__global__ __launch_bounds__(256) void scan_p3_kernel() {
    const int* deg; int n, chunk, pbase; int *rs, *cur;
    scan_map(blockIdx.x, deg, n, chunk, pbase, rs, cur);
    int t = threadIdx.x;
    int lo = chunk * CHUNK;
    int vals[4];
    int s = 0;
#pragma unroll
    for (int i = 0; i < 4; i++) {
        int idx = lo + t * 4 + i;
        vals[i] = (idx < n) ? deg[idx] : 0;
        s += vals[i];
    }
    __shared__ int sm[256];
    sm[t] = s;
    __syncthreads();
#pragma unroll
    for (int off = 1; off < 256; off <<= 1) {
        int u = (t >= off) ? sm[t - off] : 0;
        __syncthreads();
        sm[t] += u;
        __syncthreads();
    }
    int off0 = g_part[pbase + chunk] + sm[t] - s;
#pragma unroll
    for (int i = 0; i < 4; i++) {
        int idx = lo + t * 4 + i;
        if (idx < n) {
            rs[idx] = off0;
            cur[idx] = off0;
            off0 += vals[i];
        }
    }
}

// ---------------------------------------------------------------------
// fill_a: CSR buckets + src degrees for ba and aa edge types (gather_a deps)
// ---------------------------------------------------------------------
__global__ void fill_a_kernel(const int* __restrict__ src_ba, const int* __restrict__ dst_ba,
                              const int* __restrict__ src_aa, const int* __restrict__ dst_aa) {
    int i = blockIdx.x * blockDim.x + threadIdx.x;
    if (i >= EE) return;
    int s, p;
    s = src_ba[i];
    atomicAdd(&g_deg_s_ba[s], 1);
    p = atomicAdd(&g_cur_ba[dst_ba[i]], 1); g_csr_ba[p] = s;
    s = src_aa[i];
    atomicAdd(&g_deg_s_aa[s], 1);
    p = atomicAdd(&g_cur_aa[dst_aa[i]], 1); g_csr_aa[p] = s;
}

// fill_b: CSR bucket + src degrees for ab edge type (gather_b dep, side stream)
__global__ void fill_b_kernel(const int* __restrict__ src_ab, const int* __restrict__ dst_ab) {
    int i = blockIdx.x * blockDim.x + threadIdx.x;
    if (i >= EE) return;
    int s = src_ab[i];
    atomicAdd(&g_deg_s_ab[s], 1);
    int p = atomicAdd(&g_cur_ab[dst_ab[i]], 1);
    g_csr_ab[p] = s;
}

// ---------------------------------------------------------------------
// Persistent fused GEMM (unchanged from R13)
// ---------------------------------------------------------------------
__global__ __launch_bounds__(256) void gemm_all_kernel(const float* __restrict__ xa,
                                                       const float* __restrict__ xb,
                                                       const float* __restrict__ Wab,
                                                       const float* __restrict__ Wba,
                                                       const float* __restrict__ Waa) {
    extern __shared__ char smem[];
    __half* Ah    = reinterpret_cast<__half*>(smem);                       // [64][AH_LD]
    __half* Wba_s = reinterpret_cast<__half*>(smem + SMEM_AH);             // [128][WH_LD]
    __half* Waa_s = reinterpret_cast<__half*>(smem + SMEM_AH + SMEM_W1);
    __half* Wab_s = reinterpret_cast<__half*>(smem + SMEM_AH + 2 * SMEM_W1);
    float*  St    = reinterpret_cast<float*>(smem + SMEM_AH + 3 * SMEM_W1); // [8][16*20]

    const int t = threadIdx.x;
    const int warp = t >> 5;
    const int lane = t & 31;
    const int wr = warp & 3;
    const int wn = warp >> 2;

    {
        const float* Wsrc[3] = {Wba, Waa, Wab};
        __half* Wdst[3] = {Wba_s, Waa_s, Wab_s};
#pragma unroll
        for (int w = 0; w < 3; w++) {
#pragma unroll 4
            for (int i = t; i < 128 * 32; i += 256) {
                int r = i >> 5;
                int c4 = (i & 31) * 4;
                float4 v = *reinterpret_cast<const float4*>(&Wsrc[w][(size_t)r * DIM + c4]);
                __half2 h0 = __floats2half2_rn(v.x, v.y);
                __half2 h1 = __floats2half2_rn(v.z, v.w);
                uint2 u = make_uint2(*reinterpret_cast<unsigned*>(&h0),
                                     *reinterpret_cast<unsigned*>(&h1));
                *reinterpret_cast<uint2*>(&Wdst[w][r * WH_LD + c4]) = u;
            }
        }
    }

    float* st = St + warp * (16 * 20);

    for (int tile = blockIdx.x; tile < NTILES; tile += GEMM_GRID) {
        const float* X;
        int row0, nrows;
        bool dual;
        if (tile < NTB) { X = xb; row0 = tile * 64; nrows = NB; dual = false; }
        else            { X = xa; row0 = (tile - NTB) * 64; nrows = NA; dual = true; }

        __syncthreads();
#pragma unroll
        for (int i = t; i < 64 * 32; i += 256) {
            int r = i >> 5;
            int c4 = (i & 31) * 4;
            float4 v = make_float4(0.f, 0.f, 0.f, 0.f);
            if (row0 + r < nrows)
                v = *reinterpret_cast<const float4*>(&X[(size_t)(row0 + r) * DIM + c4]);
            __half2 h0 = __floats2half2_rn(v.x, v.y);
            __half2 h1 = __floats2half2_rn(v.z, v.w);
            uint2 u = make_uint2(*reinterpret_cast<unsigned*>(&h0),
                                 *reinterpret_cast<unsigned*>(&h1));
            *reinterpret_cast<uint2*>(&Ah[r * AH_LD + c4]) = u;
        }
        __syncthreads();

        int grow0 = row0 + wr * 16;
        bool rowsValid = (grow0 + 16 <= nrows);

        for (int pass = 0; pass < (dual ? 2 : 1); pass++) {
            const __half* Wsm = dual ? (pass == 0 ? Waa_s : Wab_s) : Wba_s;
            __half* Hout = dual ? (pass == 0 ? g_h_aa : g_h_ab) : g_h_ba;

            wmma::fragment<wmma::accumulator, 16, 16, 16, float> acc[4];
#pragma unroll
            for (int n = 0; n < 4; n++) wmma::fill_fragment(acc[n], 0.f);

#pragma unroll
            for (int k = 0; k < 8; k++) {
                wmma::fragment<wmma::matrix_a, 16, 16, 16, __half, wmma::row_major> a;
                wmma::load_matrix_sync(a, &Ah[(wr * 16) * AH_LD + k * 16], AH_LD);
#pragma unroll
                for (int n = 0; n < 4; n++) {
                    wmma::fragment<wmma::matrix_b, 16, 16, 16, __half, wmma::row_major> b;
                    wmma::load_matrix_sync(b, &Wsm[(k * 16) * WH_LD + (wn * 4 + n) * 16], WH_LD);
                    wmma::mma_sync(acc[n], a, b, acc[n]);
                }
            }

            if (rowsValid) {
#pragma unroll
                for (int n = 0; n < 4; n++) {
                    wmma::store_matrix_sync(st, acc[n], 20, wmma::mem_row_major);
                    __syncwarp();
                    int r = lane >> 1;
                    int c0 = (lane & 1) * 8;
                    __half2 hp[4];
#pragma unroll
                    for (int j = 0; j < 4; j++)
                        hp[j] = __floats2half2_rn(st[r * 20 + c0 + 2 * j],
                                                  st[r * 20 + c0 + 2 * j + 1]);
                    uint4 u = make_uint4(*reinterpret_cast<unsigned*>(&hp[0]),
                                         *reinterpret_cast<unsigned*>(&hp[1]),
                                         *reinterpret_cast<unsigned*>(&hp[2]),
                                         *reinterpret_cast<unsigned*>(&hp[3]));
                    *reinterpret_cast<uint4*>(
                        &Hout[(size_t)(grow0 + r) * DIM + (wn * 4 + n) * 16 + c0]) = u;
                    __syncwarp();
                }
            }
        }
    }
}

// ---------------------------------------------------------------------
// Warp-per-node gather; fp16 h rows, fp32 accumulation.
// ---------------------------------------------------------------------
__device__ __forceinline__ float4 gather_accum(const int* __restrict__ csr,
                                               const int* __restrict__ deg_s,
                                               int start, int cnt,
                                               const __half* __restrict__ h, int lane) {
    float4 acc = make_float4(0.f, 0.f, 0.f, 0.f);
    int j = 0;
    while (j < cnt) {
        int m = min(32, cnt - j);
        int idx = 0;
        float inv = 0.f;
        if (lane < m) {
            idx = __ldcs(&csr[start + j + lane]);
            inv = rsqrtf((float)deg_s[idx]);
        }
#pragma unroll 8
        for (int k = 0; k < m; k++) {
            int s = __shfl_sync(0xffffffffu, idx, k);
            float iv = __shfl_sync(0xffffffffu, inv, k);
            uint2 u = *reinterpret_cast<const uint2*>(&h[(size_t)s * DIM + lane * 4]);
            __half2 p0 = *reinterpret_cast<__half2*>(&u.x);
            __half2 p1 = *reinterpret_cast<__half2*>(&u.y);
            float2 f0 = __half22float2(p0);
            float2 f1 = __half22float2(p1);
            acc.x += f0.x * iv; acc.y += f0.y * iv;
            acc.z += f1.x * iv; acc.w += f1.y * iv;
        }
        j += m;
    }
    return acc;
}

__global__ __launch_bounds__(256) void gather_a_kernel(float* __restrict__ out_a) {
    int gw = blockIdx.x * (blockDim.x >> 5) + (threadIdx.x >> 5);
    int lane = threadIdx.x & 31;
    if (gw >= NA) return;
    int d = gw;
    int c_ba = g_deg_t_ba[d];
    int c_aa = g_deg_t_aa[d];
    float4 s_ba = gather_accum(g_csr_ba, g_deg_s_ba, g_rs_ba[d], c_ba, g_h_ba, lane);
    float4 s_aa = gather_accum(g_csr_aa, g_deg_s_aa, g_rs_aa[d], c_aa, g_h_aa, lane);
    float rb = (c_ba > 0) ? rsqrtf((float)c_ba) * 0.5f : 0.f;
    float ra = (c_aa > 0) ? rsqrtf((float)c_aa) * 0.5f : 0.f;
    float4 v;
    v.x = fmaxf(s_ba.x * rb + s_aa.x * ra, 0.f);
    v.y = fmaxf(s_ba.y * rb + s_aa.y * ra, 0.f);
    v.z = fmaxf(s_ba.z * rb + s_aa.z * ra, 0.f);
    v.w = fmaxf(s_ba.w * rb + s_aa.w * ra, 0.f);
    __stcs(reinterpret_cast<float4*>(&out_a[(size_t)d * DIM + lane * 4]), v);
}

__global__ __launch_bounds__(256) void gather_b_kernel(float* __restrict__ out_b) {
    int gw = blockIdx.x * (blockDim.x >> 5) + (threadIdx.x >> 5);
    int lane = threadIdx.x & 31;
    if (gw >= NB) return;
    int d = gw;
    int c_ab = g_deg_t_ab[d];
    float4 s_ab = gather_accum(g_csr_ab, g_deg_s_ab, g_rs_ab[d], c_ab, g_h_ab, lane);
    float r = (c_ab > 0) ? rsqrtf((float)c_ab) : 0.f;
    float4 v;
    v.x = fmaxf(s_ab.x * r, 0.f);
    v.y = fmaxf(s_ab.y * r, 0.f);
    v.z = fmaxf(s_ab.z * r, 0.f);
    v.w = fmaxf(s_ab.w * r, 0.f);
    __stcs(reinterpret_cast<float4*>(&out_b[(size_t)d * DIM + lane * 4]), v);
}

// ---------------------------------------------------------------------
extern "C" void kernel_launch(void* const* d_in, const int* in_sizes, int n_in,
                              void* d_out, int out_size) {
    const float* x_a  = (const float*)d_in[0];
    const float* x_b  = (const float*)d_in[1];
    const float* W_ab = (const float*)d_in[2];
    const float* W_ba = (const float*)d_in[3];
    const float* W_aa = (const float*)d_in[4];
    const int* src_ab = (const int*)d_in[5];
    const int* dst_ab = (const int*)d_in[6];
    const int* src_ba = (const int*)d_in[7];
    const int* dst_ba = (const int*)d_in[8];
    const int* src_aa = (const int*)d_in[9];
    const int* dst_aa = (const int*)d_in[10];

    float* out   = (float*)d_out;
    float* out_a = out;                       // [NA,128]
    float* out_b = out + (size_t)NA * DIM;    // [NB,128]

    // ---- fork: side stream runs the fused persistent GEMM ----
    cudaEventRecord(g_evFork, 0);
    cudaStreamWaitEvent(g_s1, g_evFork, 0);

    gemm_all_kernel<<<GEMM_GRID, 256, GEMM_SMEM, g_s1>>>(x_a, x_b, W_ab, W_ba, W_aa);
    cudaEventRecord(g_evGemm, g_s1);

    // ---- main stream: CSR build (a-side deps only) ----
    zero_kernel<<<512, 256>>>();
    degree_dst_kernel<<<(EE + 255) / 256, 256>>>(dst_ab, dst_ba, dst_aa);
    scan_p1_kernel<<<NCH_TOT, 256>>>();
    scan_p2_kernel<<<3, 128>>>();
    scan_p3_kernel<<<NCH_TOT, 256>>>();
    cudaEventRecord(g_evScan, 0);            // cursors ready (incl. ab)
    fill_a_kernel<<<(EE + 255) / 256, 256>>>(src_ba, dst_ba, src_aa, dst_aa);

    // gather_a on main: CSR_a in-stream + h via event
    cudaStreamWaitEvent(0, g_evGemm, 0);
    gather_a_kernel<<<(NA + 7) / 8, 256>>>(out_a);

    // side: after GEMM, build ab CSR (needs scan) then gather_b
    cudaStreamWaitEvent(g_s1, g_evScan, 0);
    fill_b_kernel<<<(EE + 255) / 256, 256, 0, g_s1>>>(src_ab, dst_ab);
    gather_b_kernel<<<(NB + 7) / 8, 256, 0, g_s1>>>(out_b);
    cudaEventRecord(g_evTailB, g_s1);

    // join
    cudaStreamWaitEvent(0, g_evTailB, 0);
}